// round 14
// baseline (speedup 1.0000x reference)
#include <cuda_runtime.h>
#include <cuda_bf16.h>
#include <cuda_fp16.h>
#include <cstdint>

// ---------------------------------------------------------------------------
// Problem constants
// ---------------------------------------------------------------------------
#define BB      2
#define LL      4096
#define DMODEL  768
#define DSTATE  16
#define DCONV   4
#define DINNER  1536
#define DTRANK  48
#define NTOT    (BB*LL)              // 8192
#define EPROJ   (DTRANK + 2*DSTATE)  // 80

// gemm1 smem geometry (fp16 2-pass: A hi+lo planes, B hi plane only)
#define PITCH_A   48
#define SLOT_A    (128*PITCH_A)            // 6144 per plane
#define STAGE_G1  (3*SLOT_A)               // 18432
#define SMEM_G1   (2*STAGE_G1)             // 36864

// ---------------------------------------------------------------------------
// Scratch
// ---------------------------------------------------------------------------
__device__ __half    g_hidh[NTOT*DMODEL];          // hidden fp16 hi plane only
__device__ __half    g_inph[2*DINNER*DMODEL];      // in_proj fp16 hi plane
__device__ __half    g_inpl[2*DINNER*DMODEL];      // in_proj fp16 lo plane

__device__ uint32_t g_outp_p[DMODEL*DINNER];       // out_proj fp16 packed
__device__ uint32_t g_xpa_p [EPROJ*DINNER];        // bf16 packed
__device__ uint32_t g_xpb_p [EPROJ*DINNER];
__device__ uint32_t g_dtpa_p[DINNER*DTRANK];       // fp16 packed
__device__ uint32_t g_dtpb_p[DINNER*DTRANK];

__device__ float    g_xz   [2*DINNER*NTOT];        // in_proj out fp32 (x | z)
__device__ uint32_t g_xca_p[DINNER*NTOT];          // conv+silu a, bf16 packed
__device__ uint32_t g_xcb_p[DINNER*NTOT];
__device__ uint32_t g_dtina[DTRANK*NTOT];          // fp16 packed
__device__ uint32_t g_dtinb[DTRANK*NTOT];
__device__ float    g_bca  [2*DSTATE*NTOT];        // interleaved {B,C} fp32
__device__ float    g_bcb  [2*DSTATE*NTOT];
__device__ uint32_t g_da_p [DINNER*NTOT];          // delta bf16 packed
__device__ uint32_t g_db_p [DINNER*NTOT];
__device__ float    g_ya   [DINNER*NTOT];
__device__ float    g_yb   [DINNER*NTOT];
__device__ uint32_t g_yp   [DINNER*NTOT];          // gated y, fp16 packed

// ---------------------------------------------------------------------------
// Helpers
// ---------------------------------------------------------------------------
__device__ __forceinline__ float softplus_f(float x) {
    return (x > 20.f) ? x : log1pf(__expf(x));
}
__device__ __forceinline__ float silu_f(float x) {
    return x / (1.f + __expf(-x));
}
__device__ __forceinline__ uint32_t pack_bf2(float x) {
    __nv_bfloat16 h = __float2bfloat16(x);
    __nv_bfloat16 l = __float2bfloat16(x - __bfloat162float(h));
    return ((uint32_t)__bfloat16_as_ushort(l) << 16) |
           (uint32_t)__bfloat16_as_ushort(h);
}
__device__ __forceinline__ float unpack_bf2(uint32_t w) {
    return __bfloat162float(__ushort_as_bfloat16((unsigned short)(w & 0xffffu))) +
           __bfloat162float(__ushort_as_bfloat16((unsigned short)(w >> 16)));
}
__device__ __forceinline__ void split_hl16(float x, __half& h, __half& l) {
    h = __float2half_rn(x);
    l = __float2half_rn(x - __half2float(h));
}
__device__ __forceinline__ uint32_t hpack(__half a, __half b) {
    return ((uint32_t)__half_as_ushort(b) << 16) | (uint32_t)__half_as_ushort(a);
}
__device__ __forceinline__ uint32_t pack_f16x2(float x) {
    __half h, l; split_hl16(x, h, l);
    return ((uint32_t)__half_as_ushort(l) << 16) | (uint32_t)__half_as_ushort(h);
}
__device__ __forceinline__ void mma_bf16(float c[4], const uint32_t a[4], const uint32_t b[2]) {
    asm volatile(
        "mma.sync.aligned.m16n8k16.row.col.f32.bf16.bf16.f32 "
        "{%0,%1,%2,%3}, {%4,%5,%6,%7}, {%8,%9}, {%0,%1,%2,%3};"
        : "+f"(c[0]), "+f"(c[1]), "+f"(c[2]), "+f"(c[3])
        : "r"(a[0]), "r"(a[1]), "r"(a[2]), "r"(a[3]), "r"(b[0]), "r"(b[1]));
}
__device__ __forceinline__ void mma_f16(float c[4], const uint32_t a[4], const uint32_t b[2]) {
    asm volatile(
        "mma.sync.aligned.m16n8k16.row.col.f32.f16.f16.f32 "
        "{%0,%1,%2,%3}, {%4,%5,%6,%7}, {%8,%9}, {%0,%1,%2,%3};"
        : "+f"(c[0]), "+f"(c[1]), "+f"(c[2]), "+f"(c[3])
        : "r"(a[0]), "r"(a[1]), "r"(a[2]), "r"(a[3]), "r"(b[0]), "r"(b[1]));
}
template<bool F16>
__device__ __forceinline__ void mma_any(float c[4], const uint32_t a[4], const uint32_t b[2]) {
    if (F16) mma_f16(c, a, b); else mma_bf16(c, a, b);
}
__device__ __forceinline__ uint32_t smem_u32(const void* p) {
    uint32_t a;
    asm("{ .reg .u64 t; cvta.to.shared.u64 t, %1; cvt.u32.u64 %0, t; }"
        : "=r"(a) : "l"(p));
    return a;
}
__device__ __forceinline__ void ldsm_x4(uint32_t* r, uint32_t a) {
    asm volatile("ldmatrix.sync.aligned.m8n8.x4.shared.b16 {%0,%1,%2,%3}, [%4];"
                 : "=r"(r[0]), "=r"(r[1]), "=r"(r[2]), "=r"(r[3]) : "r"(a));
}
__device__ __forceinline__ void cp16(uint32_t dst, const void* src) {
    asm volatile("cp.async.ca.shared.global [%0], [%1], 16;" :: "r"(dst), "l"(src));
}
#define CP_COMMIT() asm volatile("cp.async.commit_group;" ::: "memory")
#define CP_WAIT1()  asm volatile("cp.async.wait_group 1;" ::: "memory")

// ---------------------------------------------------------------------------
// gemm1: C[m][n] = in_proj(3072x768) @ hidden^T(768x8192), fp16 2-pass.
// (R12-proven config: 128x128 tile, 512 threads, A hi+lo planes, B hi only.)
// ---------------------------------------------------------------------------
__global__ __launch_bounds__(512, 1)
void gemm1_f16(const __half* __restrict__ Ah, const __half* __restrict__ Al,
               const __half* __restrict__ Bh, float* __restrict__ C)
{
    extern __shared__ __align__(16) char smem[];
    const int tid  = threadIdx.x;
    const int w    = tid >> 5;
    const int wm   = w >> 2;
    const int wn   = w & 3;
    const int lane = tid & 31;
    const int gq   = lane >> 2;
    const int t    = lane & 3;
    const int l7   = lane & 7;
    const int mg   = lane >> 3;
    const int m0   = blockIdx.y * 128;
    const int n0   = blockIdx.x * 128;
    const uint32_t sbase = smem_u32(smem);

    const uint32_t aoff =
        (uint32_t)((wm*32 + l7 + ((mg & 1) << 3)) * PITCH_A + ((mg >> 1) << 4));
    const uint32_t boff =
        (uint32_t)((wn*32 + l7 + ((mg >> 1) << 3)) * PITCH_A + ((mg & 1) << 4));

    float acc[2][4][4];
#pragma unroll
    for (int i = 0; i < 2; ++i)
#pragma unroll
        for (int j = 0; j < 4; ++j)
#pragma unroll
            for (int c = 0; c < 4; ++c) acc[i][j][c] = 0.f;

    auto issue = [&](int st, int k0) {
        uint32_t sb = sbase + st*STAGE_G1;
        {
            int c = tid;
            int plane = c >> 8, row = (c >> 1) & 127, half = c & 1;
            const __half* src =
                (plane ? Al : Ah) + (long)(m0 + row)*DMODEL + k0 + half*8;
            cp16(sb + plane*SLOT_A + row*PITCH_A + half*16, src);
        }
        if (tid < 256) {
            int c = tid;
            int row = (c >> 1) & 127, half = c & 1;
            const __half* src = Bh + (long)(n0 + row)*DMODEL + k0 + half*8;
            cp16(sb + 2*SLOT_A + row*PITCH_A + half*16, src);
        }
    };

    const int iters = DMODEL / 16;   // 48
    issue(0, 0);  CP_COMMIT();
    issue(1, 16); CP_COMMIT();

    for (int it = 0; it < iters; ++it) {
        CP_WAIT1();
        __syncthreads();

        const uint32_t st = sbase + (it & 1)*STAGE_G1;
        const uint32_t bb = st + 2*SLOT_A + boff;

        uint32_t bh[4][2];
        {
            uint32_t r[4];
            ldsm_x4(r, bb);
            bh[0][0]=r[0]; bh[0][1]=r[1]; bh[1][0]=r[2]; bh[1][1]=r[3];
            ldsm_x4(r, bb + 16*PITCH_A);
            bh[2][0]=r[0]; bh[2][1]=r[1]; bh[3][0]=r[2]; bh[3][1]=r[3];
        }

#pragma unroll
        for (int mt = 0; mt < 2; ++mt) {
            uint32_t ah[4], al[4];
            ldsm_x4(ah, st + aoff + mt*16*PITCH_A);
            ldsm_x4(al, st + SLOT_A + aoff + mt*16*PITCH_A);
#pragma unroll
            for (int nt = 0; nt < 4; ++nt) mma_f16(acc[mt][nt], ah, bh[nt]);
#pragma unroll
            for (int nt = 0; nt < 4; ++nt) mma_f16(acc[mt][nt], al, bh[nt]);
        }

        __syncthreads();
        if (it + 2 < iters) issue(it & 1, (it + 2) * 16);
        CP_COMMIT();
    }

#pragma unroll
    for (int mt = 0; mt < 2; ++mt) {
#pragma unroll
        for (int nt = 0; nt < 4; ++nt) {
            int gm = m0 + wm*32 + mt*16 + gq;
            int gn = n0 + wn*32 + nt*8 + 2*t;
            C[(long)gm*NTOT + gn]         = acc[mt][nt][0];
            C[(long)gm*NTOT + gn + 1]     = acc[mt][nt][1];
            C[(long)(gm+8)*NTOT + gn]     = acc[mt][nt][2];
            C[(long)(gm+8)*NTOT + gn + 1] = acc[mt][nt][3];
        }
    }
}

// ---------------------------------------------------------------------------
// Packed-uint2 GEMM (R12).  Element uint32 = (lo<<16)|hi, val=hi+lo.
//   F16: fp16 halves + fp16 MMA (else bf16).  PASSES: 3 (hh,hl,lh) or 2 (hh,lh).
//   EPI 0: fp32 C (CT: C[n][m]).  EPI 1: softplus+bias -> packed C2 (bf16).
//   EPI 2: rows<48 -> fp16 packed C2 ; rows 48..79 -> interleaved {B,C} fp32 C.
// ---------------------------------------------------------------------------
struct GArgs {
    const uint32_t* A;
    const uint32_t* B;
    float*          C;
    uint32_t*       C2;
    const float*    bias;
};

template<int EPI, bool TB, bool CT, bool F16, int PASSES>
__global__ __launch_bounds__(256, 2)
void gemm_mma(GArgs g0, GArgs g1, int M, int N, int K,
              int lda, int ldb, int ldc)
{
    __shared__ __align__(16) uint2 sA[2][8][132];
    __shared__ __align__(16) uint2 sB[2][8][132];

    const GArgs ga = blockIdx.z ? g1 : g0;
    const uint32_t* __restrict__ A = ga.A;
    const uint32_t* __restrict__ B = ga.B;

    const int tid  = threadIdx.x;
    const int w    = tid >> 5;
    const int wm   = w >> 2;
    const int wn   = w & 3;
    const int lane = tid & 31;
    const int g    = lane >> 2;
    const int t    = lane & 3;
    const int m0   = blockIdx.y * 128;
    const int n0   = blockIdx.x * 128;

    float acc[4][4][4];
#pragma unroll
    for (int i = 0; i < 4; ++i)
#pragma unroll
        for (int j = 0; j < 4; ++j)
#pragma unroll
            for (int c = 0; c < 4; ++c) acc[i][j][c] = 0.f;

    uint4 ra[2];
    uint4 rb[2];

    auto loadA = [&](int k0) {
#pragma unroll
        for (int p = 0; p < 2; ++p) {
            int idx = tid + p*256;
            int m  = idx >> 2;
            int kq = idx & 3;
            int gm = m0 + m;
            ra[p] = (gm < M) ? *(const uint4*)(A + (long)gm*lda + k0 + 4*kq)
                             : make_uint4(0,0,0,0);
        }
    };
    auto loadB = [&](int k0) {
        if (!TB) {
            int kp = tid >> 5;
            int nf = tid & 31;
            rb[0] = *(const uint4*)(B + (long)(k0 + 2*kp)*ldb + n0 + 4*nf);
            rb[1] = *(const uint4*)(B + (long)(k0 + 2*kp + 1)*ldb + n0 + 4*nf);
        } else {
#pragma unroll
            for (int p = 0; p < 2; ++p) {
                int idx = tid + p*256;
                int n  = idx >> 2;
                int kq = idx & 3;
                rb[p] = *(const uint4*)(B + (long)(n0 + n)*ldb + k0 + 4*kq);
            }
        }
    };
    auto stsA = [&](int st) {
#pragma unroll
        for (int p = 0; p < 2; ++p) {
            int idx = tid + p*256;
            int m  = idx >> 2;
            int kq = idx & 3;
            uint4 v = ra[p];
            sA[st][2*kq  ][m] = make_uint2(__byte_perm(v.x, v.y, 0x5410),
                                           __byte_perm(v.x, v.y, 0x7632));
            sA[st][2*kq+1][m] = make_uint2(__byte_perm(v.z, v.w, 0x5410),
                                           __byte_perm(v.z, v.w, 0x7632));
        }
    };
    auto stsB = [&](int st) {
        if (!TB) {
            int kp = tid >> 5;
            int nf = tid & 31;
            uint4 r0 = rb[0], r1 = rb[1];
            uint4 o0, o1;
            o0.x = __byte_perm(r0.x, r1.x, 0x5410); o0.y = __byte_perm(r0.x, r1.x, 0x7632);
            o0.z = __byte_perm(r0.y, r1.y, 0x5410); o0.w = __byte_perm(r0.y, r1.y, 0x7632);
            o1.x = __byte_perm(r0.z, r1.z, 0x5410); o1.y = __byte_perm(r0.z, r1.z, 0x7632);
            o1.z = __byte_perm(r0.w, r1.w, 0x5410); o1.w = __byte_perm(r0.w, r1.w, 0x7632);
            *(uint4*)&sB[st][kp][4*nf]     = o0;
            *(uint4*)&sB[st][kp][4*nf + 2] = o1;
        } else {
#pragma unroll
            for (int p = 0; p < 2; ++p) {
                int idx = tid + p*256;
                int n  = idx >> 2;
                int kq = idx & 3;
                uint4 v = rb[p];
                sB[st][2*kq  ][n] = make_uint2(__byte_perm(v.x, v.y, 0x5410),
                                               __byte_perm(v.x, v.y, 0x7632));
                sB[st][2*kq+1][n] = make_uint2(__byte_perm(v.z, v.w, 0x5410),
                                               __byte_perm(v.z, v.w, 0x7632));
            }
        }
    };

    loadA(0); loadB(0);
    stsA(0);  stsB(0);
    __syncthreads();

    const int iters = K / 16;
    for (int it = 0; it < iters; ++it) {
        const int cur  = it & 1;
        const bool more = (it + 1 < iters);
        if (more) { loadA((it+1)*16); loadB((it+1)*16); }

        uint32_t bh[4][2], bl[4][2];
#pragma unroll
        for (int nt = 0; nt < 4; ++nt) {
            int nn = wn*32 + nt*8 + g;
            uint2 p0 = sB[cur][t  ][nn];
            uint2 p1 = sB[cur][t+4][nn];
            bh[nt][0] = p0.x; bl[nt][0] = p0.y;
            bh[nt][1] = p1.x; bl[nt][1] = p1.y;
        }
#pragma unroll
        for (int mt = 0; mt < 4; ++mt) {
            int mm = wm*64 + mt*16 + g;
            uint2 a0 = sA[cur][t  ][mm];
            uint2 a1 = sA[cur][t  ][mm+8];
            uint2 a2 = sA[cur][t+4][mm];
            uint2 a3 = sA[cur][t+4][mm+8];
            uint32_t ah[4] = { a0.x, a1.x, a2.x, a3.x };
            uint32_t al[4] = { a0.y, a1.y, a2.y, a3.y };
#pragma unroll
            for (int nt = 0; nt < 4; ++nt) mma_any<F16>(acc[mt][nt], ah, bh[nt]);
            if (PASSES == 3) {
#pragma unroll
                for (int nt = 0; nt < 4; ++nt) mma_any<F16>(acc[mt][nt], ah, bl[nt]);
            }
#pragma unroll
            for (int nt = 0; nt < 4; ++nt) mma_any<F16>(acc[mt][nt], al, bh[nt]);
        }

        if (more) {
            stsA(cur ^ 1); stsB(cur ^ 1);
            __syncthreads();
        }
    }

    // ---- epilogue ----
#pragma unroll
    for (int mt = 0; mt < 4; ++mt) {
#pragma unroll
        for (int nt = 0; nt < 4; ++nt) {
            int gm = m0 + wm*64 + mt*16 + g;
            int gn = n0 + wn*32 + nt*8 + 2*t;
            float c0 = acc[mt][nt][0], c1 = acc[mt][nt][1];
            float c2 = acc[mt][nt][2], c3 = acc[mt][nt][3];
            if (EPI == 0) {
                if (!CT) {
                    if (gm < M) {
                        ga.C[(long)gm*ldc + gn]     = c0;
                        ga.C[(long)gm*ldc + gn + 1] = c1;
                    }
                    if (gm + 8 < M) {
                        ga.C[(long)(gm+8)*ldc + gn]     = c2;
                        ga.C[(long)(gm+8)*ldc + gn + 1] = c3;
                    }
                } else {
                    if (gm < M) {
                        ga.C[(long)gn*ldc + gm]       = c0;
                        ga.C[(long)(gn+1)*ldc + gm]   = c1;
                    }
                    if (gm + 8 < M) {
                        ga.C[(long)gn*ldc + gm + 8]     = c2;
                        ga.C[(long)(gn+1)*ldc + gm + 8] = c3;
                    }
                }
            } else if (EPI == 1) {
                if (gm < M) {
                    float b0 = ga.bias[gm];
                    ga.C2[(long)gm*ldc + gn]     = pack_bf2(softplus_f(c0 + b0));
                    ga.C2[(long)gm*ldc + gn + 1] = pack_bf2(softplus_f(c1 + b0));
                }
                if (gm + 8 < M) {
                    float b1 = ga.bias[gm + 8];
                    ga.C2[(long)(gm+8)*ldc + gn]     = pack_bf2(softplus_f(c2 + b1));
                    ga.C2[(long)(gm+8)*ldc + gn + 1] = pack_bf2(softplus_f(c3 + b1));
                }
            } else { // EPI 2: dt rows -> fp16 packed; rows 48..79 -> interleaved {B,C}
                if (gm < DTRANK) {
                    ga.C2[(long)gm*ldc + gn]     = pack_f16x2(c0);
                    ga.C2[(long)gm*ldc + gn + 1] = pack_f16x2(c1);
                } else if (gm < EPROJ) {
                    int r = gm - DTRANK, s = r & 15, wch = r >> 4;
                    ga.C[(((long)gn*16 + s) << 1) + wch]       = c0;
                    ga.C[(((long)(gn+1)*16 + s) << 1) + wch]   = c1;
                }
                if (gm + 8 < DTRANK) {
                    ga.C2[(long)(gm+8)*ldc + gn]     = pack_f16x2(c2);
                    ga.C2[(long)(gm+8)*ldc + gn + 1] = pack_f16x2(c3);
                } else if (gm + 8 < EPROJ) {
                    int r = gm + 8 - DTRANK, s = r & 15, wch = r >> 4;
                    ga.C[(((long)gn*16 + s) << 1) + wch]       = c2;
                    ga.C[(((long)(gn+1)*16 + s) << 1) + wch]   = c3;
                }
            }
        }
    }
}

// ---------------------------------------------------------------------------
// Split kernels.
// ---------------------------------------------------------------------------
__global__ void split_g1(const float* hid, __half* hidH, long c0,
                         const float* inp, __half* inpH, __half* inpL, long c1,
                         const float* outp, uint32_t* outP, long c2)
{
    long q = ((long)blockIdx.x * blockDim.x + threadIdx.x) * 4;
    int mode;
    const float* s;
    if      (q < c0)              { s = hid;  mode = 0; }
    else if ((q -= c0) < c1)      { s = inp;  mode = 1; }
    else if ((q -= c1) < c2)      { s = outp; mode = 2; }
    else return;
    float4 v = *(const float4*)(s + q);
    float vv[4] = {v.x, v.y, v.z, v.w};
    __half h[4], l[4];
#pragma unroll
    for (int j = 0; j < 4; ++j) split_hl16(vv[j], h[j], l[j]);
    if (mode == 0) {
        *(uint2*)(hidH + q) = make_uint2(hpack(h[0],h[1]), hpack(h[2],h[3]));
    } else if (mode == 1) {
        *(uint2*)(inpH + q) = make_uint2(hpack(h[0],h[1]), hpack(h[2],h[3]));
        *(uint2*)(inpL + q) = make_uint2(hpack(l[0],l[1]), hpack(l[2],l[3]));
    } else {
        uint4 o;
        o.x = hpack(h[0], l[0]); o.y = hpack(h[1], l[1]);
        o.z = hpack(h[2], l[2]); o.w = hpack(h[3], l[3]);
        *(uint4*)(outP + q) = o;
    }
}

// xproj -> bf16 packed; dtproj -> fp16 packed
__global__ void split_multi4(const float* s0, uint32_t* d0, long c0,
                             const float* s1, uint32_t* d1, long c1,
                             const float* s2, uint32_t* d2, long c2,
                             const float* s3, uint32_t* d3, long c3)
{
    long q = ((long)blockIdx.x * blockDim.x + threadIdx.x) * 4;
    const float* s; uint32_t* d; bool f16;
    if      (q < c0) { s = s0; d = d0; f16 = false; }
    else if ((q -= c0) < c1) { s = s1; d = d1; f16 = false; }
    else if ((q -= c1) < c2) { s = s2; d = d2; f16 = true; }
    else if ((q -= c2) < c3) { s = s3; d = d3; f16 = true; }
    else return;
    float4 v = *(const float4*)(s + q);
    uint4 o;
    if (f16) {
        o.x = pack_f16x2(v.x); o.y = pack_f16x2(v.y);
        o.z = pack_f16x2(v.z); o.w = pack_f16x2(v.w);
    } else {
        o.x = pack_bf2(v.x); o.y = pack_bf2(v.y);
        o.z = pack_bf2(v.z); o.w = pack_bf2(v.w);
    }
    *(uint4*)(d + q) = o;
}

// ---------------------------------------------------------------------------
// Fused depthwise conv(w=4)+SiLU, both branches, bf16 packed output (R4).
// ---------------------------------------------------------------------------
__global__ __launch_bounds__(256)
void conv_silu_both(const float* __restrict__ x,
                    const float* __restrict__ wa, const float* __restrict__ ba,
                    const float* __restrict__ wb, const float* __restrict__ bb,
                    uint32_t* __restrict__ oa, uint32_t* __restrict__ ob)
{
    long q = (long)blockIdx.x * blockDim.x + threadIdx.x;
    const long PERD = NTOT/4;
    int d  = (int)(q / PERD);
    int n4 = (int)(q % PERD);
    int n  = n4 * 4;
    int b  = n / LL;
    int l0 = n % LL;

    const float* xr = x + (long)d*NTOT + (long)b*LL;
    float4 prev = (l0 >= 4)      ? *(const float4*)(xr + l0 - 4) : make_float4(0,0,0,0);
    float4 cur  =                  *(const float4*)(xr + l0);
    float4 next = (l0 + 4 < LL)  ? *(const float4*)(xr + l0 + 4) : make_float4(0,0,0,0);

    float xa[8] = {prev.x, prev.y, prev.z, prev.w, cur.x, cur.y, cur.z, cur.w};
    float xb[8] = {cur.x, cur.y, cur.z, cur.w, next.x, next.y, next.z, next.w};

    float wav[4], wbv[4];
#pragma unroll
    for (int k = 0; k < 4; ++k) { wav[k] = wa[d*4+k]; wbv[k] = wb[d*4+k]; }
    float bav = ba[d], bbv = bb[d];

    uint4 outa, outb;
    uint32_t* pa = &outa.x;
    uint32_t* pb = &outb.x;
#pragma unroll
    for (int j = 0; j < 4; ++j) {
        float sa = bav, sb = bbv;
#pragma unroll
        for (int k = 0; k < 4; ++k) {
            sa = fmaf(wav[k], xa[j + 1 + k], sa);
            sb = fmaf(wbv[k], xb[j + 3 - k], sb);
        }
        pa[j] = pack_bf2(silu_f(sa));
        pb[j] = pack_bf2(silu_f(sb));
    }
    *(uint4*)(oa + (long)d*NTOT + n) = outa;
    *(uint4*)(ob + (long)d*NTOT + n) = outb;
}

// ---------------------------------------------------------------------------
// Selective scan with depth-1 prefetch. One warp = two units (d, d+768),
// same (branch,b). bc layout: float2 {B,C} at [(b*LL + l)*16 + state].
// ---------------------------------------------------------------------------
__global__ __launch_bounds__(256)
void scan_both(const uint32_t* __restrict__ ua, const uint32_t* __restrict__ da,
               const float* __restrict__ bca, const float* __restrict__ Ala,
               const float* __restrict__ Dva, float* __restrict__ ya,
               const uint32_t* __restrict__ ub, const uint32_t* __restrict__ db,
               const float* __restrict__ bcb, const float* __restrict__ Alb,
               const float* __restrict__ Dvb, float* __restrict__ yb)
{
    const int lane   = threadIdx.x & 31;
    const int lane16 = lane & 15;
    const int h      = lane >> 4;
    int warpId = blockIdx.x * (blockDim.x >> 5) + (threadIdx.x >> 5);

    const int branch = warpId / (BB * (DINNER/2));
    int rem = warpId % (BB * (DINNER/2));
    const int b  = rem / (DINNER/2);
    const int dp = rem % (DINNER/2);
    const int d  = dp + h * (DINNER/2);

    const uint32_t* uP = branch ? ub : ua;
    const uint32_t* dP = branch ? db : da;
    const float*    bc = branch ? bcb : bca;
    const float*    Al = branch ? Alb : Ala;
    const float*    Dv = branch ? Dvb : Dva;
    float*          yP = branch ? yb : ya;
    const bool fwd = (branch == 0);

    long base = (long)d*NTOT + (long)b*LL;
    const uint32_t* uR = uP + base;
    const uint32_t* dR = dP + base;
    const float2*   bcR = (const float2*)bc + ((long)b*LL)*16 + lane16;
    float* yR = yP + base;

    float A  = -__expf(Al[d*DSTATE + lane16]);
    float Dd = Dv[d];
    float hS = 0.f;

    int l0 = fwd ? 0 : LL - 4;
    uint4  u4 = *(const uint4*)(uR + l0);
    uint4  d4 = *(const uint4*)(dR + l0);
    float2 s0 = bcR[(long)(l0+0)*16];
    float2 s1 = bcR[(long)(l0+1)*16];
    float2 s2 = bcR[(long)(l0+2)*16];
    float2 s3 = bcR[(long)(l0+3)*16];

    for (int q = 0; q < LL/4; ++q) {
        int l0n = fwd ? (q+1)*4 : (LL - 8 - q*4);
        uint4 u4n = make_uint4(0,0,0,0), d4n = make_uint4(0,0,0,0);
        float2 t0 = make_float2(0,0), t1 = t0, t2 = t0, t3 = t0;
        if (q + 1 < LL/4) {
            u4n = *(const uint4*)(uR + l0n);
            d4n = *(const uint4*)(dR + l0n);
            t0 = bcR[(long)(l0n+0)*16];
            t1 = bcR[(long)(l0n+1)*16];
            t2 = bcR[(long)(l0n+2)*16];
            t3 = bcR[(long)(l0n+3)*16];
        }
        float uu[4] = {unpack_bf2(u4.x), unpack_bf2(u4.y), unpack_bf2(u4.z), unpack_bf2(u4.w)};
        float dd[4] = {unpack_bf2(d4.x), unpack_bf2(d4.y), unpack_bf2(d4.z), unpack_bf2(d4.w)};
        float Bv[4] = {s0.x, s1.x, s2.x, s3.x};
        float Cv[4] = {s0.y, s1.y, s2.y, s3.y};
        float yout[4];
#pragma unroll
        for (int j = 0; j < 4; ++j) {
            int jj = fwd ? j : 3 - j;
            float ut = uu[jj];
            float dt = dd[jj];
            float dA = __expf(dt * A);
            hS = fmaf(dA, hS, dt * ut * Bv[jj]);
            float p = hS * Cv[jj];
            p += __shfl_xor_sync(0xffffffffu, p, 1);
            p += __shfl_xor_sync(0xffffffffu, p, 2);
            p += __shfl_xor_sync(0xffffffffu, p, 4);
            p += __shfl_xor_sync(0xffffffffu, p, 8);
            yout[jj] = fmaf(ut, Dd, p);
        }
        if (lane16 == 0)
            *(float4*)(yR + l0) = make_float4(yout[0], yout[1], yout[2], yout[3]);
        u4 = u4n; d4 = d4n;
        s0 = t0; s1 = t1; s2 = t2; s3 = t3; l0 = l0n;
    }
}

// ---------------------------------------------------------------------------
// Combine: y = (ya + yb) * silu(z) -> fp16 packed (gemm7 operand)
// ---------------------------------------------------------------------------
__global__ void combine_kernel(const float* __restrict__ ya,
                               const float* __restrict__ yb,
                               const float* __restrict__ xz,
                               uint32_t* __restrict__ y)
{
    long q = ((long)blockIdx.x * blockDim.x + threadIdx.x) * 4;
    if (q >= (long)DINNER*NTOT) return;
    float4 a = *(const float4*)(ya + q);
    float4 b = *(const float4*)(yb + q);
    float4 z = *(const float4*)(xz + (long)DINNER*NTOT + q);
    uint4 o;
    o.x = pack_f16x2((a.x + b.x) * silu_f(z.x));
    o.y = pack_f16x2((a.y + b.y) * silu_f(z.y));
    o.z = pack_f16x2((a.z + b.z) * silu_f(z.z));
    o.w = pack_f16x2((a.w + b.w) * silu_f(z.w));
    *(uint4*)(y + q) = o;
}

// ---------------------------------------------------------------------------
// Host launcher
// ---------------------------------------------------------------------------
template<typename T>
static T* sym_addr(const void* sym) {
    void* p = nullptr;
    cudaGetSymbolAddress(&p, sym);
    return (T*)p;
}

extern "C" void kernel_launch(void* const* d_in, const int* in_sizes, int n_in,
                              void* d_out, int out_size)
{
    const float* hidden    = (const float*)d_in[0];
    const float* in_proj   = (const float*)d_in[1];
    const float* out_proj  = (const float*)d_in[2];
    const float* conv_w_a  = (const float*)d_in[3];
    const float* conv_b_a  = (const float*)d_in[4];
    const float* conv_w_b  = (const float*)d_in[5];
    const float* conv_b_b  = (const float*)d_in[6];
    const float* xproj_a   = (const float*)d_in[7];
    const float* xproj_b   = (const float*)d_in[8];
    const float* dtproj_a  = (const float*)d_in[9];
    const float* dtproj_b  = (const float*)d_in[10];
    const float* dtbias_a  = (const float*)d_in[11];
    const float* dtbias_b  = (const float*)d_in[12];
    const float* A_a_log   = (const float*)d_in[13];
    const float* A_b_log   = (const float*)d_in[14];
    const float* D_a       = (const float*)d_in[15];
    const float* D_b       = (const float*)d_in[16];
    float* out             = (float*)d_out;

    __half* hidh = sym_addr<__half>(g_hidh);
    __half* inph = sym_addr<__half>(g_inph);
    __half* inpl = sym_addr<__half>(g_inpl);
    uint32_t* outp_p = sym_addr<uint32_t>(g_outp_p);
    uint32_t* xpa_p  = sym_addr<uint32_t>(g_xpa_p);
    uint32_t* xpb_p  = sym_addr<uint32_t>(g_xpb_p);
    uint32_t* dtpa_p = sym_addr<uint32_t>(g_dtpa_p);
    uint32_t* dtpb_p = sym_addr<uint32_t>(g_dtpb_p);
    float*    xz     = sym_addr<float>(g_xz);
    uint32_t* xca_p  = sym_addr<uint32_t>(g_xca_p);
    uint32_t* xcb_p  = sym_addr<uint32_t>(g_xcb_p);
    uint32_t* dtina  = sym_addr<uint32_t>(g_dtina);
    uint32_t* dtinb  = sym_addr<uint32_t>(g_dtinb);
    float*    bca    = sym_addr<float>(g_bca);
    float*    bcb    = sym_addr<float>(g_bcb);
    uint32_t* da_p   = sym_addr<uint32_t>(g_da_p);
    uint32_t* db_p   = sym_addr<uint32_t>(g_db_p);
    float*    ya     = sym_addr<float>(g_ya);
    float*    yb     = sym_addr<float>(g_yb);
    uint32_t* yp     = sym_addr<uint32_t>(g_yp);

    cudaFuncSetAttribute(gemm1_f16,
        cudaFuncAttributeMaxDynamicSharedMemorySize, SMEM_G1);

    // 0a) hidden -> fp16 hi plane; in_proj -> fp16 hi/lo; out_proj -> fp16 packed
    {
        long c0 = (long)NTOT*DMODEL;
        long c1 = (long)2*DINNER*DMODEL;
        long c2 = (long)DMODEL*DINNER;
        int blocks = (int)(((c0 + c1 + c2)/4 + 255) / 256);
        split_g1<<<blocks, 256>>>(hidden, hidh, c0,
                                  in_proj, inph, inpl, c1,
                                  out_proj, outp_p, c2);
    }
    // 0b) xproj -> bf16 packed; dtproj -> fp16 packed
    {
        long c0 = (long)EPROJ*DINNER;
        long c1 = (long)EPROJ*DINNER;
        long c2 = (long)DINNER*DTRANK;
        long c3 = (long)DINNER*DTRANK;
        long total = c0+c1+c2+c3;
        int blocks = (int)((total/4 + 255) / 256);
        split_multi4<<<blocks, 256>>>(xproj_a, xpa_p, c0, xproj_b, xpb_p, c1,
                                      dtproj_a, dtpa_p, c2, dtproj_b, dtpb_p, c3);
    }

    // 1) xz = in_proj @ hidden^T (fp16 2-pass, fp32 out)
    {
        dim3 grid(NTOT/128, (2*DINNER)/128);
        gemm1_f16<<<grid, 512, SMEM_G1>>>(inph, inpl, hidh, xz);
    }

    // 2) conv + SiLU, both branches -> bf16 packed
    {
        long total = (long)DINNER*NTOT/4;
        conv_silu_both<<<(int)(total/256), 256>>>(xz, conv_w_a, conv_b_a,
                                                  conv_w_b, conv_b_b, xca_p, xcb_p);
    }

    // 3) x_proj both branches (bf16 3-pass): dt rows fp16 packed, B/C interleaved
    {
        GArgs a{xpa_p, xca_p, bca, dtina, nullptr};
        GArgs b{xpb_p, xcb_p, bcb, dtinb, nullptr};
        dim3 grid(NTOT/128, 1, 2);
        gemm_mma<2,false,false,false,3><<<grid, 256>>>(a, b, EPROJ, NTOT, DINNER,
                                                       DINNER, NTOT, NTOT);
    }

    // 4) delta = softplus(dtproj @ dtin + bias) -> bf16 packed (fp16 2-pass)
    {
        GArgs a{dtpa_p, dtina, nullptr, da_p, dtbias_a};
        GArgs b{dtpb_p, dtinb, nullptr, db_p, dtbias_b};
        dim3 grid(NTOT/128, DINNER/128, 2);
        gemm_mma<1,false,false,true,2><<<grid, 256>>>(a, b, DINNER, NTOT, DTRANK,
                                                      DTRANK, NTOT, NTOT);
    }

    // 5) both scans in one launch (depth-1 prefetch)
    {
        int warps  = 2 * BB * (DINNER/2);
        int blocks = warps / 8;
        scan_both<<<blocks, 256>>>(xca_p, da_p, bca, A_a_log, D_a, ya,
                                   xcb_p, db_p, bcb, A_b_log, D_b, yb);
    }

    // 6) combine + gate -> fp16 packed
    {
        long total = (long)DINNER*NTOT/4;
        combine_kernel<<<(int)((total + 255)/256), 256>>>(ya, yb, xz, yp);
    }

    // 7) out^T: out_proj @ y, stored C[n][o]  (fp16 2-pass)
    {
        GArgs ga{outp_p, yp, out, nullptr, nullptr};
        dim3 grid(NTOT/128, DMODEL/128, 1);
        gemm_mma<0,false,true,true,2><<<grid, 256>>>(ga, ga, DMODEL, NTOT, DINNER,
                                                     DINNER, NTOT, DMODEL);
    }
}

// round 15
// speedup vs baseline: 1.1949x; 1.1949x over previous
#include <cuda_runtime.h>
#include <cuda_bf16.h>
#include <cuda_fp16.h>
#include <cstdint>

// ---------------------------------------------------------------------------
// Problem constants
// ---------------------------------------------------------------------------
#define BB      2
#define LL      4096
#define DMODEL  768
#define DSTATE  16
#define DCONV   4
#define DINNER  1536
#define DTRANK  48
#define NTOT    (BB*LL)              // 8192
#define EPROJ   (DTRANK + 2*DSTATE)  // 80

// gemm1 smem geometry (fp16 2-pass: A hi+lo planes, B hi plane only)
#define PITCH_A   48
#define SLOT_A    (128*PITCH_A)            // 6144 per plane
#define STAGE_G1  (3*SLOT_A)               // 18432
#define SMEM_G1   (2*STAGE_G1)             // 36864

// ---------------------------------------------------------------------------
// Scratch
// ---------------------------------------------------------------------------
__device__ __half    g_hidh[NTOT*DMODEL];          // hidden fp16 hi plane only
__device__ __half    g_inph[2*DINNER*DMODEL];      // in_proj fp16 hi plane
__device__ __half    g_inpl[2*DINNER*DMODEL];      // in_proj fp16 lo plane

__device__ uint32_t g_outp_p[DMODEL*DINNER];       // out_proj fp16 packed
__device__ uint32_t g_xpa_p [EPROJ*DINNER];        // bf16 packed
__device__ uint32_t g_xpb_p [EPROJ*DINNER];
__device__ uint32_t g_dtpa_p[DINNER*DTRANK];       // fp16 packed
__device__ uint32_t g_dtpb_p[DINNER*DTRANK];

__device__ float    g_xz   [2*DINNER*NTOT];        // in_proj out fp32 (x | z)
__device__ uint32_t g_xca_p[DINNER*NTOT];          // conv+silu a, bf16 packed
__device__ uint32_t g_xcb_p[DINNER*NTOT];
__device__ uint32_t g_dtina[DTRANK*NTOT];          // fp16 packed
__device__ uint32_t g_dtinb[DTRANK*NTOT];
__device__ float    g_bca  [2*DSTATE*NTOT];        // interleaved {B,C} fp32
__device__ float    g_bcb  [2*DSTATE*NTOT];
__device__ uint32_t g_da_p [DINNER*NTOT];          // delta bf16 packed
__device__ uint32_t g_db_p [DINNER*NTOT];
__device__ float    g_ya   [DINNER*NTOT];
__device__ float    g_yb   [DINNER*NTOT];
__device__ uint32_t g_yp   [DINNER*NTOT];          // gated y, fp16 packed

// ---------------------------------------------------------------------------
// Helpers
// ---------------------------------------------------------------------------
__device__ __forceinline__ float softplus_f(float x) {
    return (x > 20.f) ? x : log1pf(__expf(x));
}
__device__ __forceinline__ float silu_f(float x) {
    return x / (1.f + __expf(-x));
}
__device__ __forceinline__ uint32_t pack_bf2(float x) {
    __nv_bfloat16 h = __float2bfloat16(x);
    __nv_bfloat16 l = __float2bfloat16(x - __bfloat162float(h));
    return ((uint32_t)__bfloat16_as_ushort(l) << 16) |
           (uint32_t)__bfloat16_as_ushort(h);
}
__device__ __forceinline__ float unpack_bf2(uint32_t w) {
    return __bfloat162float(__ushort_as_bfloat16((unsigned short)(w & 0xffffu))) +
           __bfloat162float(__ushort_as_bfloat16((unsigned short)(w >> 16)));
}
__device__ __forceinline__ void split_hl16(float x, __half& h, __half& l) {
    h = __float2half_rn(x);
    l = __float2half_rn(x - __half2float(h));
}
__device__ __forceinline__ uint32_t hpack(__half a, __half b) {
    return ((uint32_t)__half_as_ushort(b) << 16) | (uint32_t)__half_as_ushort(a);
}
__device__ __forceinline__ uint32_t pack_f16x2(float x) {
    __half h, l; split_hl16(x, h, l);
    return ((uint32_t)__half_as_ushort(l) << 16) | (uint32_t)__half_as_ushort(h);
}
__device__ __forceinline__ void mma_bf16(float c[4], const uint32_t a[4], const uint32_t b[2]) {
    asm volatile(
        "mma.sync.aligned.m16n8k16.row.col.f32.bf16.bf16.f32 "
        "{%0,%1,%2,%3}, {%4,%5,%6,%7}, {%8,%9}, {%0,%1,%2,%3};"
        : "+f"(c[0]), "+f"(c[1]), "+f"(c[2]), "+f"(c[3])
        : "r"(a[0]), "r"(a[1]), "r"(a[2]), "r"(a[3]), "r"(b[0]), "r"(b[1]));
}
__device__ __forceinline__ void mma_f16(float c[4], const uint32_t a[4], const uint32_t b[2]) {
    asm volatile(
        "mma.sync.aligned.m16n8k16.row.col.f32.f16.f16.f32 "
        "{%0,%1,%2,%3}, {%4,%5,%6,%7}, {%8,%9}, {%0,%1,%2,%3};"
        : "+f"(c[0]), "+f"(c[1]), "+f"(c[2]), "+f"(c[3])
        : "r"(a[0]), "r"(a[1]), "r"(a[2]), "r"(a[3]), "r"(b[0]), "r"(b[1]));
}
template<bool F16>
__device__ __forceinline__ void mma_any(float c[4], const uint32_t a[4], const uint32_t b[2]) {
    if (F16) mma_f16(c, a, b); else mma_bf16(c, a, b);
}
__device__ __forceinline__ uint32_t smem_u32(const void* p) {
    uint32_t a;
    asm("{ .reg .u64 t; cvta.to.shared.u64 t, %1; cvt.u32.u64 %0, t; }"
        : "=r"(a) : "l"(p));
    return a;
}
__device__ __forceinline__ void ldsm_x4(uint32_t* r, uint32_t a) {
    asm volatile("ldmatrix.sync.aligned.m8n8.x4.shared.b16 {%0,%1,%2,%3}, [%4];"
                 : "=r"(r[0]), "=r"(r[1]), "=r"(r[2]), "=r"(r[3]) : "r"(a));
}
__device__ __forceinline__ void cp16(uint32_t dst, const void* src) {
    asm volatile("cp.async.ca.shared.global [%0], [%1], 16;" :: "r"(dst), "l"(src));
}
#define CP_COMMIT() asm volatile("cp.async.commit_group;" ::: "memory")
#define CP_WAIT1()  asm volatile("cp.async.wait_group 1;" ::: "memory")

// ---------------------------------------------------------------------------
// gemm1: C[m][n] = in_proj(3072x768) @ hidden^T(768x8192), fp16 2-pass.
// (R12-proven config: 128x128 tile, 512 threads, A hi+lo planes, B hi only.)
// ---------------------------------------------------------------------------
__global__ __launch_bounds__(512, 1)
void gemm1_f16(const __half* __restrict__ Ah, const __half* __restrict__ Al,
               const __half* __restrict__ Bh, float* __restrict__ C)
{
    extern __shared__ __align__(16) char smem[];
    const int tid  = threadIdx.x;
    const int w    = tid >> 5;
    const int wm   = w >> 2;
    const int wn   = w & 3;
    const int lane = tid & 31;
    const int gq   = lane >> 2;
    const int t    = lane & 3;
    const int l7   = lane & 7;
    const int mg   = lane >> 3;
    const int m0   = blockIdx.y * 128;
    const int n0   = blockIdx.x * 128;
    const uint32_t sbase = smem_u32(smem);

    const uint32_t aoff =
        (uint32_t)((wm*32 + l7 + ((mg & 1) << 3)) * PITCH_A + ((mg >> 1) << 4));
    const uint32_t boff =
        (uint32_t)((wn*32 + l7 + ((mg >> 1) << 3)) * PITCH_A + ((mg & 1) << 4));

    float acc[2][4][4];
#pragma unroll
    for (int i = 0; i < 2; ++i)
#pragma unroll
        for (int j = 0; j < 4; ++j)
#pragma unroll
            for (int c = 0; c < 4; ++c) acc[i][j][c] = 0.f;

    auto issue = [&](int st, int k0) {
        uint32_t sb = sbase + st*STAGE_G1;
        {
            int c = tid;
            int plane = c >> 8, row = (c >> 1) & 127, half = c & 1;
            const __half* src =
                (plane ? Al : Ah) + (long)(m0 + row)*DMODEL + k0 + half*8;
            cp16(sb + plane*SLOT_A + row*PITCH_A + half*16, src);
        }
        if (tid < 256) {
            int c = tid;
            int row = (c >> 1) & 127, half = c & 1;
            const __half* src = Bh + (long)(n0 + row)*DMODEL + k0 + half*8;
            cp16(sb + 2*SLOT_A + row*PITCH_A + half*16, src);
        }
    };

    const int iters = DMODEL / 16;   // 48
    issue(0, 0);  CP_COMMIT();
    issue(1, 16); CP_COMMIT();

    for (int it = 0; it < iters; ++it) {
        CP_WAIT1();
        __syncthreads();

        const uint32_t st = sbase + (it & 1)*STAGE_G1;
        const uint32_t bb = st + 2*SLOT_A + boff;

        uint32_t bh[4][2];
        {
            uint32_t r[4];
            ldsm_x4(r, bb);
            bh[0][0]=r[0]; bh[0][1]=r[1]; bh[1][0]=r[2]; bh[1][1]=r[3];
            ldsm_x4(r, bb + 16*PITCH_A);
            bh[2][0]=r[0]; bh[2][1]=r[1]; bh[3][0]=r[2]; bh[3][1]=r[3];
        }

#pragma unroll
        for (int mt = 0; mt < 2; ++mt) {
            uint32_t ah[4], al[4];
            ldsm_x4(ah, st + aoff + mt*16*PITCH_A);
            ldsm_x4(al, st + SLOT_A + aoff + mt*16*PITCH_A);
#pragma unroll
            for (int nt = 0; nt < 4; ++nt) mma_f16(acc[mt][nt], ah, bh[nt]);
#pragma unroll
            for (int nt = 0; nt < 4; ++nt) mma_f16(acc[mt][nt], al, bh[nt]);
        }

        __syncthreads();
        if (it + 2 < iters) issue(it & 1, (it + 2) * 16);
        CP_COMMIT();
    }

#pragma unroll
    for (int mt = 0; mt < 2; ++mt) {
#pragma unroll
        for (int nt = 0; nt < 4; ++nt) {
            int gm = m0 + wm*32 + mt*16 + gq;
            int gn = n0 + wn*32 + nt*8 + 2*t;
            C[(long)gm*NTOT + gn]         = acc[mt][nt][0];
            C[(long)gm*NTOT + gn + 1]     = acc[mt][nt][1];
            C[(long)(gm+8)*NTOT + gn]     = acc[mt][nt][2];
            C[(long)(gm+8)*NTOT + gn + 1] = acc[mt][nt][3];
        }
    }
}

// ---------------------------------------------------------------------------
// Packed-uint2 GEMM (R12).  Element uint32 = (lo<<16)|hi, val=hi+lo.
//   F16: fp16 halves + fp16 MMA (else bf16).  PASSES: 3 (hh,hl,lh) or 2 (hh,lh).
//   EPI 0: fp32 C (CT: C[n][m]).  EPI 1: softplus+bias -> packed C2 (bf16).
//   EPI 2: rows<48 -> fp16 packed C2 ; rows 48..79 -> interleaved {B,C} fp32 C.
// ---------------------------------------------------------------------------
struct GArgs {
    const uint32_t* A;
    const uint32_t* B;
    float*          C;
    uint32_t*       C2;
    const float*    bias;
};

template<int EPI, bool TB, bool CT, bool F16, int PASSES>
__global__ __launch_bounds__(256, 2)
void gemm_mma(GArgs g0, GArgs g1, int M, int N, int K,
              int lda, int ldb, int ldc)
{
    __shared__ __align__(16) uint2 sA[2][8][132];
    __shared__ __align__(16) uint2 sB[2][8][132];

    const GArgs ga = blockIdx.z ? g1 : g0;
    const uint32_t* __restrict__ A = ga.A;
    const uint32_t* __restrict__ B = ga.B;

    const int tid  = threadIdx.x;
    const int w    = tid >> 5;
    const int wm   = w >> 2;
    const int wn   = w & 3;
    const int lane = tid & 31;
    const int g    = lane >> 2;
    const int t    = lane & 3;
    const int m0   = blockIdx.y * 128;
    const int n0   = blockIdx.x * 128;

    float acc[4][4][4];
#pragma unroll
    for (int i = 0; i < 4; ++i)
#pragma unroll
        for (int j = 0; j < 4; ++j)
#pragma unroll
            for (int c = 0; c < 4; ++c) acc[i][j][c] = 0.f;

    uint4 ra[2];
    uint4 rb[2];

    auto loadA = [&](int k0) {
#pragma unroll
        for (int p = 0; p < 2; ++p) {
            int idx = tid + p*256;
            int m  = idx >> 2;
            int kq = idx & 3;
            int gm = m0 + m;
            ra[p] = (gm < M) ? *(const uint4*)(A + (long)gm*lda + k0 + 4*kq)
                             : make_uint4(0,0,0,0);
        }
    };
    auto loadB = [&](int k0) {
        if (!TB) {
            int kp = tid >> 5;
            int nf = tid & 31;
            rb[0] = *(const uint4*)(B + (long)(k0 + 2*kp)*ldb + n0 + 4*nf);
            rb[1] = *(const uint4*)(B + (long)(k0 + 2*kp + 1)*ldb + n0 + 4*nf);
        } else {
#pragma unroll
            for (int p = 0; p < 2; ++p) {
                int idx = tid + p*256;
                int n  = idx >> 2;
                int kq = idx & 3;
                rb[p] = *(const uint4*)(B + (long)(n0 + n)*ldb + k0 + 4*kq);
            }
        }
    };
    auto stsA = [&](int st) {
#pragma unroll
        for (int p = 0; p < 2; ++p) {
            int idx = tid + p*256;
            int m  = idx >> 2;
            int kq = idx & 3;
            uint4 v = ra[p];
            sA[st][2*kq  ][m] = make_uint2(__byte_perm(v.x, v.y, 0x5410),
                                           __byte_perm(v.x, v.y, 0x7632));
            sA[st][2*kq+1][m] = make_uint2(__byte_perm(v.z, v.w, 0x5410),
                                           __byte_perm(v.z, v.w, 0x7632));
        }
    };
    auto stsB = [&](int st) {
        if (!TB) {
            int kp = tid >> 5;
            int nf = tid & 31;
            uint4 r0 = rb[0], r1 = rb[1];
            uint4 o0, o1;
            o0.x = __byte_perm(r0.x, r1.x, 0x5410); o0.y = __byte_perm(r0.x, r1.x, 0x7632);
            o0.z = __byte_perm(r0.y, r1.y, 0x5410); o0.w = __byte_perm(r0.y, r1.y, 0x7632);
            o1.x = __byte_perm(r0.z, r1.z, 0x5410); o1.y = __byte_perm(r0.z, r1.z, 0x7632);
            o1.z = __byte_perm(r0.w, r1.w, 0x5410); o1.w = __byte_perm(r0.w, r1.w, 0x7632);
            *(uint4*)&sB[st][kp][4*nf]     = o0;
            *(uint4*)&sB[st][kp][4*nf + 2] = o1;
        } else {
#pragma unroll
            for (int p = 0; p < 2; ++p) {
                int idx = tid + p*256;
                int n  = idx >> 2;
                int kq = idx & 3;
                uint4 v = rb[p];
                sB[st][2*kq  ][n] = make_uint2(__byte_perm(v.x, v.y, 0x5410),
                                               __byte_perm(v.x, v.y, 0x7632));
                sB[st][2*kq+1][n] = make_uint2(__byte_perm(v.z, v.w, 0x5410),
                                               __byte_perm(v.z, v.w, 0x7632));
            }
        }
    };

    loadA(0); loadB(0);
    stsA(0);  stsB(0);
    __syncthreads();

    const int iters = K / 16;
    for (int it = 0; it < iters; ++it) {
        const int cur  = it & 1;
        const bool more = (it + 1 < iters);
        if (more) { loadA((it+1)*16); loadB((it+1)*16); }

        uint32_t bh[4][2], bl[4][2];
#pragma unroll
        for (int nt = 0; nt < 4; ++nt) {
            int nn = wn*32 + nt*8 + g;
            uint2 p0 = sB[cur][t  ][nn];
            uint2 p1 = sB[cur][t+4][nn];
            bh[nt][0] = p0.x; bl[nt][0] = p0.y;
            bh[nt][1] = p1.x; bl[nt][1] = p1.y;
        }
#pragma unroll
        for (int mt = 0; mt < 4; ++mt) {
            int mm = wm*64 + mt*16 + g;
            uint2 a0 = sA[cur][t  ][mm];
            uint2 a1 = sA[cur][t  ][mm+8];
            uint2 a2 = sA[cur][t+4][mm];
            uint2 a3 = sA[cur][t+4][mm+8];
            uint32_t ah[4] = { a0.x, a1.x, a2.x, a3.x };
            uint32_t al[4] = { a0.y, a1.y, a2.y, a3.y };
#pragma unroll
            for (int nt = 0; nt < 4; ++nt) mma_any<F16>(acc[mt][nt], ah, bh[nt]);
            if (PASSES == 3) {
#pragma unroll
                for (int nt = 0; nt < 4; ++nt) mma_any<F16>(acc[mt][nt], ah, bl[nt]);
            }
#pragma unroll
            for (int nt = 0; nt < 4; ++nt) mma_any<F16>(acc[mt][nt], al, bh[nt]);
        }

        if (more) {
            stsA(cur ^ 1); stsB(cur ^ 1);
            __syncthreads();
        }
    }

    // ---- epilogue ----
#pragma unroll
    for (int mt = 0; mt < 4; ++mt) {
#pragma unroll
        for (int nt = 0; nt < 4; ++nt) {
            int gm = m0 + wm*64 + mt*16 + g;
            int gn = n0 + wn*32 + nt*8 + 2*t;
            float c0 = acc[mt][nt][0], c1 = acc[mt][nt][1];
            float c2 = acc[mt][nt][2], c3 = acc[mt][nt][3];
            if (EPI == 0) {
                if (!CT) {
                    if (gm < M) {
                        ga.C[(long)gm*ldc + gn]     = c0;
                        ga.C[(long)gm*ldc + gn + 1] = c1;
                    }
                    if (gm + 8 < M) {
                        ga.C[(long)(gm+8)*ldc + gn]     = c2;
                        ga.C[(long)(gm+8)*ldc + gn + 1] = c3;
                    }
                } else {
                    if (gm < M) {
                        ga.C[(long)gn*ldc + gm]       = c0;
                        ga.C[(long)(gn+1)*ldc + gm]   = c1;
                    }
                    if (gm + 8 < M) {
                        ga.C[(long)gn*ldc + gm + 8]     = c2;
                        ga.C[(long)(gn+1)*ldc + gm + 8] = c3;
                    }
                }
            } else if (EPI == 1) {
                if (gm < M) {
                    float b0 = ga.bias[gm];
                    ga.C2[(long)gm*ldc + gn]     = pack_bf2(softplus_f(c0 + b0));
                    ga.C2[(long)gm*ldc + gn + 1] = pack_bf2(softplus_f(c1 + b0));
                }
                if (gm + 8 < M) {
                    float b1 = ga.bias[gm + 8];
                    ga.C2[(long)(gm+8)*ldc + gn]     = pack_bf2(softplus_f(c2 + b1));
                    ga.C2[(long)(gm+8)*ldc + gn + 1] = pack_bf2(softplus_f(c3 + b1));
                }
            } else { // EPI 2: dt rows -> fp16 packed; rows 48..79 -> interleaved {B,C}
                if (gm < DTRANK) {
                    ga.C2[(long)gm*ldc + gn]     = pack_f16x2(c0);
                    ga.C2[(long)gm*ldc + gn + 1] = pack_f16x2(c1);
                } else if (gm < EPROJ) {
                    int r = gm - DTRANK, s = r & 15, wch = r >> 4;
                    ga.C[(((long)gn*16 + s) << 1) + wch]       = c0;
                    ga.C[(((long)(gn+1)*16 + s) << 1) + wch]   = c1;
                }
                if (gm + 8 < DTRANK) {
                    ga.C2[(long)(gm+8)*ldc + gn]     = pack_f16x2(c2);
                    ga.C2[(long)(gm+8)*ldc + gn + 1] = pack_f16x2(c3);
                } else if (gm + 8 < EPROJ) {
                    int r = gm + 8 - DTRANK, s = r & 15, wch = r >> 4;
                    ga.C[(((long)gn*16 + s) << 1) + wch]       = c2;
                    ga.C[(((long)(gn+1)*16 + s) << 1) + wch]   = c3;
                }
            }
        }
    }
}

// ---------------------------------------------------------------------------
// Split kernels.
// ---------------------------------------------------------------------------
__global__ void split_g1(const float* hid, __half* hidH, long c0,
                         const float* inp, __half* inpH, __half* inpL, long c1,
                         const float* outp, uint32_t* outP, long c2)
{
    long q = ((long)blockIdx.x * blockDim.x + threadIdx.x) * 4;
    int mode;
    const float* s;
    if      (q < c0)              { s = hid;  mode = 0; }
    else if ((q -= c0) < c1)      { s = inp;  mode = 1; }
    else if ((q -= c1) < c2)      { s = outp; mode = 2; }
    else return;
    float4 v = *(const float4*)(s + q);
    float vv[4] = {v.x, v.y, v.z, v.w};
    __half h[4], l[4];
#pragma unroll
    for (int j = 0; j < 4; ++j) split_hl16(vv[j], h[j], l[j]);
    if (mode == 0) {
        *(uint2*)(hidH + q) = make_uint2(hpack(h[0],h[1]), hpack(h[2],h[3]));
    } else if (mode == 1) {
        *(uint2*)(inpH + q) = make_uint2(hpack(h[0],h[1]), hpack(h[2],h[3]));
        *(uint2*)(inpL + q) = make_uint2(hpack(l[0],l[1]), hpack(l[2],l[3]));
    } else {
        uint4 o;
        o.x = hpack(h[0], l[0]); o.y = hpack(h[1], l[1]);
        o.z = hpack(h[2], l[2]); o.w = hpack(h[3], l[3]);
        *(uint4*)(outP + q) = o;
    }
}

// xproj -> bf16 packed; dtproj -> fp16 packed
__global__ void split_multi4(const float* s0, uint32_t* d0, long c0,
                             const float* s1, uint32_t* d1, long c1,
                             const float* s2, uint32_t* d2, long c2,
                             const float* s3, uint32_t* d3, long c3)
{
    long q = ((long)blockIdx.x * blockDim.x + threadIdx.x) * 4;
    const float* s; uint32_t* d; bool f16;
    if      (q < c0) { s = s0; d = d0; f16 = false; }
    else if ((q -= c0) < c1) { s = s1; d = d1; f16 = false; }
    else if ((q -= c1) < c2) { s = s2; d = d2; f16 = true; }
    else if ((q -= c2) < c3) { s = s3; d = d3; f16 = true; }
    else return;
    float4 v = *(const float4*)(s + q);
    uint4 o;
    if (f16) {
        o.x = pack_f16x2(v.x); o.y = pack_f16x2(v.y);
        o.z = pack_f16x2(v.z); o.w = pack_f16x2(v.w);
    } else {
        o.x = pack_bf2(v.x); o.y = pack_bf2(v.y);
        o.z = pack_bf2(v.z); o.w = pack_bf2(v.w);
    }
    *(uint4*)(d + q) = o;
}

// ---------------------------------------------------------------------------
// Fused depthwise conv(w=4)+SiLU, both branches, bf16 packed output (R4).
// ---------------------------------------------------------------------------
__global__ __launch_bounds__(256)
void conv_silu_both(const float* __restrict__ x,
                    const float* __restrict__ wa, const float* __restrict__ ba,
                    const float* __restrict__ wb, const float* __restrict__ bb,
                    uint32_t* __restrict__ oa, uint32_t* __restrict__ ob)
{
    long q = (long)blockIdx.x * blockDim.x + threadIdx.x;
    const long PERD = NTOT/4;
    int d  = (int)(q / PERD);
    int n4 = (int)(q % PERD);
    int n  = n4 * 4;
    int b  = n / LL;
    int l0 = n % LL;

    const float* xr = x + (long)d*NTOT + (long)b*LL;
    float4 prev = (l0 >= 4)      ? *(const float4*)(xr + l0 - 4) : make_float4(0,0,0,0);
    float4 cur  =                  *(const float4*)(xr + l0);
    float4 next = (l0 + 4 < LL)  ? *(const float4*)(xr + l0 + 4) : make_float4(0,0,0,0);

    float xa[8] = {prev.x, prev.y, prev.z, prev.w, cur.x, cur.y, cur.z, cur.w};
    float xb[8] = {cur.x, cur.y, cur.z, cur.w, next.x, next.y, next.z, next.w};

    float wav[4], wbv[4];
#pragma unroll
    for (int k = 0; k < 4; ++k) { wav[k] = wa[d*4+k]; wbv[k] = wb[d*4+k]; }
    float bav = ba[d], bbv = bb[d];

    uint4 outa, outb;
    uint32_t* pa = &outa.x;
    uint32_t* pb = &outb.x;
#pragma unroll
    for (int j = 0; j < 4; ++j) {
        float sa = bav, sb = bbv;
#pragma unroll
        for (int k = 0; k < 4; ++k) {
            sa = fmaf(wav[k], xa[j + 1 + k], sa);
            sb = fmaf(wbv[k], xb[j + 3 - k], sb);
        }
        pa[j] = pack_bf2(silu_f(sa));
        pb[j] = pack_bf2(silu_f(sb));
    }
    *(uint4*)(oa + (long)d*NTOT + n) = outa;
    *(uint4*)(ob + (long)d*NTOT + n) = outb;
}

// ---------------------------------------------------------------------------
// Selective scan (R12/R4 register-lean version, NO prefetch).
// One warp = two units (d, d+768), same (branch,b).
// bc layout: float2 {B,C} at [(b*LL + l)*16 + state].
// ---------------------------------------------------------------------------
__global__ __launch_bounds__(256)
void scan_both(const uint32_t* __restrict__ ua, const uint32_t* __restrict__ da,
               const float* __restrict__ bca, const float* __restrict__ Ala,
               const float* __restrict__ Dva, float* __restrict__ ya,
               const uint32_t* __restrict__ ub, const uint32_t* __restrict__ db,
               const float* __restrict__ bcb, const float* __restrict__ Alb,
               const float* __restrict__ Dvb, float* __restrict__ yb)
{
    const int lane   = threadIdx.x & 31;
    const int lane16 = lane & 15;
    const int h      = lane >> 4;
    int warpId = blockIdx.x * (blockDim.x >> 5) + (threadIdx.x >> 5);

    const int branch = warpId / (BB * (DINNER/2));
    int rem = warpId % (BB * (DINNER/2));
    const int b  = rem / (DINNER/2);
    const int dp = rem % (DINNER/2);
    const int d  = dp + h * (DINNER/2);

    const uint32_t* uP = branch ? ub : ua;
    const uint32_t* dP = branch ? db : da;
    const float*    bc = branch ? bcb : bca;
    const float*    Al = branch ? Alb : Ala;
    const float*    Dv = branch ? Dvb : Dva;
    float*          yP = branch ? yb : ya;
    const bool fwd = (branch == 0);

    long base = (long)d*NTOT + (long)b*LL;
    const uint32_t* uR = uP + base;
    const uint32_t* dR = dP + base;
    const float2*   bcR = (const float2*)bc + ((long)b*LL)*16 + lane16;
    float* yR = yP + base;

    float A  = -__expf(Al[d*DSTATE + lane16]);
    float Dd = Dv[d];
    float hS = 0.f;

    for (int q = 0; q < LL/4; ++q) {
        int l0 = fwd ? q*4 : (LL - 4 - q*4);
        uint4 u4 = *(const uint4*)(uR + l0);
        uint4 d4 = *(const uint4*)(dR + l0);
        float2 s0 = bcR[(long)(l0+0)*16];
        float2 s1 = bcR[(long)(l0+1)*16];
        float2 s2 = bcR[(long)(l0+2)*16];
        float2 s3 = bcR[(long)(l0+3)*16];
        float uu[4] = {unpack_bf2(u4.x), unpack_bf2(u4.y), unpack_bf2(u4.z), unpack_bf2(u4.w)};
        float dd[4] = {unpack_bf2(d4.x), unpack_bf2(d4.y), unpack_bf2(d4.z), unpack_bf2(d4.w)};
        float Bv[4] = {s0.x, s1.x, s2.x, s3.x};
        float Cv[4] = {s0.y, s1.y, s2.y, s3.y};
        float yout[4];
#pragma unroll
        for (int j = 0; j < 4; ++j) {
            int jj = fwd ? j : 3 - j;
            float ut = uu[jj];
            float dt = dd[jj];
            float dA = __expf(dt * A);
            hS = fmaf(dA, hS, dt * ut * Bv[jj]);
            float p = hS * Cv[jj];
            p += __shfl_xor_sync(0xffffffffu, p, 1);
            p += __shfl_xor_sync(0xffffffffu, p, 2);
            p += __shfl_xor_sync(0xffffffffu, p, 4);
            p += __shfl_xor_sync(0xffffffffu, p, 8);
            yout[jj] = fmaf(ut, Dd, p);
        }
        if (lane16 == 0)
            *(float4*)(yR + l0) = make_float4(yout[0], yout[1], yout[2], yout[3]);
    }
}

// ---------------------------------------------------------------------------
// Combine: y = (ya + yb) * silu(z) -> fp16 packed (gemm7 operand)
// ---------------------------------------------------------------------------
__global__ void combine_kernel(const float* __restrict__ ya,
                               const float* __restrict__ yb,
                               const float* __restrict__ xz,
                               uint32_t* __restrict__ y)
{
    long q = ((long)blockIdx.x * blockDim.x + threadIdx.x) * 4;
    if (q >= (long)DINNER*NTOT) return;
    float4 a = *(const float4*)(ya + q);
    float4 b = *(const float4*)(yb + q);
    float4 z = *(const float4*)(xz + (long)DINNER*NTOT + q);
    uint4 o;
    o.x = pack_f16x2((a.x + b.x) * silu_f(z.x));
    o.y = pack_f16x2((a.y + b.y) * silu_f(z.y));
    o.z = pack_f16x2((a.z + b.z) * silu_f(z.z));
    o.w = pack_f16x2((a.w + b.w) * silu_f(z.w));
    *(uint4*)(y + q) = o;
}

// ---------------------------------------------------------------------------
// Host launcher
// ---------------------------------------------------------------------------
template<typename T>
static T* sym_addr(const void* sym) {
    void* p = nullptr;
    cudaGetSymbolAddress(&p, sym);
    return (T*)p;
}

extern "C" void kernel_launch(void* const* d_in, const int* in_sizes, int n_in,
                              void* d_out, int out_size)
{
    const float* hidden    = (const float*)d_in[0];
    const float* in_proj   = (const float*)d_in[1];
    const float* out_proj  = (const float*)d_in[2];
    const float* conv_w_a  = (const float*)d_in[3];
    const float* conv_b_a  = (const float*)d_in[4];
    const float* conv_w_b  = (const float*)d_in[5];
    const float* conv_b_b  = (const float*)d_in[6];
    const float* xproj_a   = (const float*)d_in[7];
    const float* xproj_b   = (const float*)d_in[8];
    const float* dtproj_a  = (const float*)d_in[9];
    const float* dtproj_b  = (const float*)d_in[10];
    const float* dtbias_a  = (const float*)d_in[11];
    const float* dtbias_b  = (const float*)d_in[12];
    const float* A_a_log   = (const float*)d_in[13];
    const float* A_b_log   = (const float*)d_in[14];
    const float* D_a       = (const float*)d_in[15];
    const float* D_b       = (const float*)d_in[16];
    float* out             = (float*)d_out;

    __half* hidh = sym_addr<__half>(g_hidh);
    __half* inph = sym_addr<__half>(g_inph);
    __half* inpl = sym_addr<__half>(g_inpl);
    uint32_t* outp_p = sym_addr<uint32_t>(g_outp_p);
    uint32_t* xpa_p  = sym_addr<uint32_t>(g_xpa_p);
    uint32_t* xpb_p  = sym_addr<uint32_t>(g_xpb_p);
    uint32_t* dtpa_p = sym_addr<uint32_t>(g_dtpa_p);
    uint32_t* dtpb_p = sym_addr<uint32_t>(g_dtpb_p);
    float*    xz     = sym_addr<float>(g_xz);
    uint32_t* xca_p  = sym_addr<uint32_t>(g_xca_p);
    uint32_t* xcb_p  = sym_addr<uint32_t>(g_xcb_p);
    uint32_t* dtina  = sym_addr<uint32_t>(g_dtina);
    uint32_t* dtinb  = sym_addr<uint32_t>(g_dtinb);
    float*    bca    = sym_addr<float>(g_bca);
    float*    bcb    = sym_addr<float>(g_bcb);
    uint32_t* da_p   = sym_addr<uint32_t>(g_da_p);
    uint32_t* db_p   = sym_addr<uint32_t>(g_db_p);
    float*    ya     = sym_addr<float>(g_ya);
    float*    yb     = sym_addr<float>(g_yb);
    uint32_t* yp     = sym_addr<uint32_t>(g_yp);

    cudaFuncSetAttribute(gemm1_f16,
        cudaFuncAttributeMaxDynamicSharedMemorySize, SMEM_G1);

    // 0a) hidden -> fp16 hi plane; in_proj -> fp16 hi/lo; out_proj -> fp16 packed
    {
        long c0 = (long)NTOT*DMODEL;
        long c1 = (long)2*DINNER*DMODEL;
        long c2 = (long)DMODEL*DINNER;
        int blocks = (int)(((c0 + c1 + c2)/4 + 255) / 256);
        split_g1<<<blocks, 256>>>(hidden, hidh, c0,
                                  in_proj, inph, inpl, c1,
                                  out_proj, outp_p, c2);
    }
    // 0b) xproj -> bf16 packed; dtproj -> fp16 packed
    {
        long c0 = (long)EPROJ*DINNER;
        long c1 = (long)EPROJ*DINNER;
        long c2 = (long)DINNER*DTRANK;
        long c3 = (long)DINNER*DTRANK;
        long total = c0+c1+c2+c3;
        int blocks = (int)((total/4 + 255) / 256);
        split_multi4<<<blocks, 256>>>(xproj_a, xpa_p, c0, xproj_b, xpb_p, c1,
                                      dtproj_a, dtpa_p, c2, dtproj_b, dtpb_p, c3);
    }

    // 1) xz = in_proj @ hidden^T (fp16 2-pass, fp32 out)
    {
        dim3 grid(NTOT/128, (2*DINNER)/128);
        gemm1_f16<<<grid, 512, SMEM_G1>>>(inph, inpl, hidh, xz);
    }

    // 2) conv + SiLU, both branches -> bf16 packed
    {
        long total = (long)DINNER*NTOT/4;
        conv_silu_both<<<(int)(total/256), 256>>>(xz, conv_w_a, conv_b_a,
                                                  conv_w_b, conv_b_b, xca_p, xcb_p);
    }

    // 3) x_proj both branches (bf16 3-pass): dt rows fp16 packed, B/C interleaved
    {
        GArgs a{xpa_p, xca_p, bca, dtina, nullptr};
        GArgs b{xpb_p, xcb_p, bcb, dtinb, nullptr};
        dim3 grid(NTOT/128, 1, 2);
        gemm_mma<2,false,false,false,3><<<grid, 256>>>(a, b, EPROJ, NTOT, DINNER,
                                                       DINNER, NTOT, NTOT);
    }

    // 4) delta = softplus(dtproj @ dtin + bias) -> bf16 packed (fp16 2-pass)
    {
        GArgs a{dtpa_p, dtina, nullptr, da_p, dtbias_a};
        GArgs b{dtpb_p, dtinb, nullptr, db_p, dtbias_b};
        dim3 grid(NTOT/128, DINNER/128, 2);
        gemm_mma<1,false,false,true,2><<<grid, 256>>>(a, b, DINNER, NTOT, DTRANK,
                                                      DTRANK, NTOT, NTOT);
    }

    // 5) both scans in one launch (register-lean, no prefetch)
    {
        int warps  = 2 * BB * (DINNER/2);
        int blocks = warps / 8;
        scan_both<<<blocks, 256>>>(xca_p, da_p, bca, A_a_log, D_a, ya,
                                   xcb_p, db_p, bcb, A_b_log, D_b, yb);
    }

    // 6) combine + gate -> fp16 packed
    {
        long total = (long)DINNER*NTOT/4;
        combine_kernel<<<(int)((total + 255)/256), 256>>>(ya, yb, xz, yp);
    }

    // 7) out^T: out_proj @ y, stored C[n][o]  (fp16 2-pass)
    {
        GArgs ga{outp_p, yp, out, nullptr, nullptr};
        dim3 grid(NTOT/128, DMODEL/128, 1);
        gemm_mma<0,false,true,true,2><<<grid, 256>>>(ga, ga, DMODEL, NTOT, DINNER,
                                                     DINNER, NTOT, DMODEL);
    }
}